// round 13
// baseline (speedup 1.0000x reference)
#include <cuda_runtime.h>
#include <cuda_bf16.h>
#include <cstdint>

// Batched 2D patch gather:
//   images:    (4096, 4096) float32
//   positions: (4096, 2)    int32   (row, col), col in [0, 3968)
//   out:       (4096, 128, 128) float32
//
// One CTA per patch, 256 threads (8 warps). Each warp copies one 512B row
// per step (lane = 16B chunk), 16 rows total per warp.
//
// Reads are ALIGNED LDG.128 from (p1 & ~3); the 0-3 float misalignment is
// repaired in registers via __shfl_down of the neighbor lane's float4 plus
// a broadcast tail load for lane 31. m = p1&3 is uniform per patch, so we
// dispatch to a compile-time specialization (no divergence).
// This cuts L1 read wavefronts ~4x vs scalar stride-16B loads.
// Stores are STG.128 streaming (__stcs) so the 256MB write stream doesn't
// evict the L2-resident 64MB image.

static constexpr int IMG_W   = 4096;
static constexpr int PATCH   = 128;
static constexpr int THREADS = 256;
static constexpr int BATCH   = 4;   // rows in flight per thread
static constexpr int NBATCH  = 4;   // BATCH*NBATCH = 16 rows per warp

template<int M>
__device__ __forceinline__ void copy_patch(const float* __restrict__ srcA,
                                           float* __restrict__ dst,
                                           int lane, int r0)
{
#pragma unroll
    for (int b = 0; b < NBATCH; ++b) {
        float4 A[BATCH], T[BATCH];
        // ---- aligned vector load phase ----
#pragma unroll
        for (int i = 0; i < BATCH; ++i) {
            const int r = (b * BATCH + i) * 8 + r0;
            const float4* rp =
                reinterpret_cast<const float4*>(srcA + (size_t)r * IMG_W);
            A[i] = __ldg(rp + lane);          // 512B aligned span: 4 wavefronts
            if (M != 0) T[i] = __ldg(rp + 32); // broadcast tail: 1 wavefront
        }
        // ---- realign + store phase ----
#pragma unroll
        for (int i = 0; i < BATCH; ++i) {
            const int r = (b * BATCH + i) * 8 + r0;
            float4 v;
            if (M == 0) {
                v = A[i];
            } else {
                float4 An;
                An.x = __shfl_down_sync(0xffffffffu, A[i].x, 1);
                An.y = __shfl_down_sync(0xffffffffu, A[i].y, 1);
                An.z = __shfl_down_sync(0xffffffffu, A[i].z, 1);
                An.w = __shfl_down_sync(0xffffffffu, A[i].w, 1);
                if (lane == 31) An = T[i];
                if      (M == 1) v = make_float4(A[i].y, A[i].z, A[i].w, An.x);
                else if (M == 2) v = make_float4(A[i].z, A[i].w, An.x, An.y);
                else             v = make_float4(A[i].w, An.x,   An.y, An.z);
            }
            __stcs(reinterpret_cast<float4*>(dst + r * PATCH) + lane, v);
        }
    }
}

__global__ __launch_bounds__(THREADS, 4)
void patch_gather_kernel(const float* __restrict__ img,
                         const int*   __restrict__ pos,
                         float*       __restrict__ out)
{
    const int n  = blockIdx.x;
    const int p0 = __ldg(&pos[2 * n]);
    const int p1 = __ldg(&pos[2 * n + 1]);
    const int m  = p1 & 3;

    const float* __restrict__ srcA = img + (size_t)p0 * IMG_W + (p1 & ~3);
    float*       __restrict__ dst  = out + (size_t)n * (PATCH * PATCH);

    const int lane = threadIdx.x & 31;
    const int r0   = threadIdx.x >> 5;

    switch (m) {
        case 0:  copy_patch<0>(srcA, dst, lane, r0); break;
        case 1:  copy_patch<1>(srcA, dst, lane, r0); break;
        case 2:  copy_patch<2>(srcA, dst, lane, r0); break;
        default: copy_patch<3>(srcA, dst, lane, r0); break;
    }
}

extern "C" void kernel_launch(void* const* d_in, const int* in_sizes, int n_in,
                              void* d_out, int out_size)
{
    const float* img = (const float*)d_in[0];
    const int*   pos = (const int*)d_in[1];
    float*       out = (float*)d_out;

    const int n_patches = in_sizes[1] / 2;   // positions is (N, 2)

    patch_gather_kernel<<<n_patches, THREADS>>>(img, pos, out);
}